// round 13
// baseline (speedup 1.0000x reference)
#include <cuda_runtime.h>
#include <cuda_fp8.h>
#include <cuda_fp16.h>
#include <cstdint>
#include <math.h>

#define Bn 8
#define Tn 256
#define Vn 32
#define Dn 256
#define CVT_PER_V 64            // converter blocks per v-slice
#define MAIN_CTAS 8192          // 4 * 64 * 32

// ---------------- device scratch (allocation-free) ----------------
__device__ float g_an[Bn * Tn];
__device__ float g_ap[Bn * Tn];
__device__ uint8_t g_fb8 [Bn * Tn * Vn * Dn];   // e4m3 feature      (x32)
__device__ uint8_t g_fab8[Bn * Tn * Vn * Dn];   // e4m3 feature_aug  (x32)
__device__ unsigned g_cntV[Vn];                  // per-v arrival counters
__device__ unsigned g_done;                      // main-CTA completion counter

// ---------------- PTX helpers (baseline ISA, sm_89/90 features) ----------------
__device__ __forceinline__ uint32_t smem_to_u32(const void* p) {
    uint32_t a;
    asm("{ .reg .u64 t; cvta.to.shared.u64 t, %1; cvt.u32.u64 %0, t; }"
        : "=r"(a) : "l"(p));
    return a;
}
#define CP_ASYNC16(saddr, gptr) \
    asm volatile("cp.async.cg.shared.global [%0], [%1], 16;" :: "r"(saddr), "l"(gptr))
#define CP_COMMIT() asm volatile("cp.async.commit_group;")
#define CP_WAIT0()  asm volatile("cp.async.wait_group 0;")
#define LDMATRIX_X4(r, addr) \
    asm volatile("ldmatrix.sync.aligned.m8n8.x4.shared.b16 {%0,%1,%2,%3}, [%4];" \
        : "=r"((r)[0]), "=r"((r)[1]), "=r"((r)[2]), "=r"((r)[3]) : "r"(addr))
#define MMA_FP8_F16(d, a, b0, b1) \
    asm volatile("mma.sync.aligned.m16n8k32.row.col.f16.e4m3.e4m3.f16 " \
        "{%0,%1}, {%2,%3,%4,%5}, {%6,%7}, {%0,%1};" \
        : "+r"((d)[0]), "+r"((d)[1]) \
        : "r"((a)[0]), "r"((a)[1]), "r"((a)[2]), "r"((a)[3]), "r"(b0), "r"(b1))

// ---------------- layout ----------------
#define A_BYTES 32768
#define B_BYTES 32768
#define SMEM_DYN (A_BYTES + B_BYTES)   // 64 KB -> 2 CTAs/SM

// ---------------- kernels ----------------
__global__ void zero_kernel() {
    int tid = threadIdx.x;
    for (int idx = tid; idx < Bn * Tn; idx += 256) { g_an[idx] = 0.f; g_ap[idx] = 0.f; }
    if (tid < Vn) g_cntV[tid] = 0u;
    if (tid == 0) g_done = 0u;
}

// v-ordered converter (PDL primary): block b -> v = b/64.
__global__ void __launch_bounds__(256) cvt_kernel(
    const float* __restrict__ f, const float* __restrict__ fa)
{
    // allow the dependent (main) grid to start launching now
    asm volatile("griddepcontrol.launch_dependents;");

    const int b   = blockIdx.x;
    const int v   = b >> 6;
    const int sub = b & 63;
    const int tid = threadIdx.x;

    // per-v word space: 2 arrays * 2048 bt-rows * 64 float4-words = 262144
    #pragma unroll
    for (int it = 0; it < 16; it++) {
        int w   = sub * 4096 + it * 256 + tid;
        int arr = (w >= 131072);
        int w2  = w & 131071;
        int bt  = w2 >> 6;
        int d4  = w2 & 63;
        size_t eidx = ((size_t)(bt * Vn + v)) * Dn + d4 * 4;
        const float* src = (arr ? fa : f) + eidx;
        float4 x = *(const float4*)src;
        x.x *= 32.f; x.y *= 32.f; x.z *= 32.f; x.w *= 32.f;
        uint32_t* dst = (uint32_t*)(arr ? g_fab8 : g_fb8);
        dst[eidx >> 2] = __nv_fp8x4_e4m3(x).__x;
    }
    __threadfence();
    __syncthreads();
    if (tid == 0) {
        unsigned r;
        asm volatile("atom.release.gpu.global.add.u32 %0, [%1], 1;"
                     : "=r"(r) : "l"(&g_cntV[v]) : "memory");
    }
}

// Main (PDL secondary): R7 tile body + per-v spin + fused loss.
// Grid (4, 64, 32): x = qt + 2*kt, y = ij, z = v (slowest).
__global__ void __launch_bounds__(256, 2) infonce_fp8h_kernel(float* __restrict__ out) {
    extern __shared__ char smem[];
    __shared__ float s_red[128];
    __shared__ unsigned s_old;

    const uint32_t aBase = smem_to_u32(smem);
    const uint32_t bBase = aBase + A_BYTES;
    const int tid  = threadIdx.x;
    const int wid  = tid >> 5;
    const int lane = tid & 31;
    const int warp_m = wid >> 1;   // 0..3 -> m*32
    const int warp_n = wid & 1;    // 0..1 -> n*64

    const int qt = blockIdx.x & 1;
    const int kt = blockIdx.x >> 1;
    const int ij = blockIdx.y;
    const int v  = blockIdx.z;
    const int i  = ij >> 3;
    const int j  = ij & 7;
    const bool diag = (i == j);

    // wait for this v-slice (converters are guaranteed to all have started)
    if (tid == 0) {
        unsigned x;
        do {
            asm volatile("ld.acquire.gpu.global.u32 %0, [%1];"
                         : "=r"(x) : "l"(&g_cntV[v]) : "memory");
            if (x < CVT_PER_V) __nanosleep(256);
        } while (x < CVT_PER_V);
    }
    __syncthreads();

    if (tid < 128) s_red[tid] = 0.f;

    const size_t RS = (size_t)Vn * Dn;
    const uint8_t* Ag = g_fb8  + ((size_t)(i * Tn + qt * 128) * Vn + v) * Dn;
    const uint8_t* Bg = g_fab8 + ((size_t)(j * Tn + kt * 128) * Vn + v) * Dn;

    #pragma unroll
    for (int it = 0; it < 8; it++) {
        int id = tid + it * 256;
        int row = id >> 4, c = id & 15;
        uint32_t soff = (uint32_t)(row * 256) + (uint32_t)((c * 16) ^ ((row & 7) << 4));
        CP_ASYNC16(aBase + soff, Ag + (size_t)row * RS + c * 16);
    }
    #pragma unroll
    for (int it = 0; it < 8; it++) {
        int id = tid + it * 256;
        int row = id >> 4, c = id & 15;
        uint32_t soff = (uint32_t)(row * 256) + (uint32_t)((c * 16) ^ ((row & 7) << 4));
        CP_ASYNC16(bBase + soff, Bg + (size_t)row * RS + c * 16);
    }
    CP_COMMIT();

    uint32_t acc[2][8][2];
    #pragma unroll
    for (int tm = 0; tm < 2; tm++)
        #pragma unroll
        for (int g = 0; g < 8; g++) { acc[tm][g][0] = 0u; acc[tm][g][1] = 0u; }

    CP_WAIT0();
    __syncthreads();

    #pragma unroll
    for (int kk = 0; kk < 8; kk++) {
        uint32_t afr[2][4];
        #pragma unroll
        for (int tm = 0; tm < 2; tm++) {
            int r = warp_m * 32 + tm * 16 + (lane & 7) + ((lane >> 3) & 1) * 8;
            uint32_t kb = (uint32_t)(kk * 32 + ((lane >> 4) & 1) * 16);
            LDMATRIX_X4(afr[tm], aBase + r * 256 + (kb ^ ((r & 7) << 4)));
        }
        #pragma unroll
        for (int gg = 0; gg < 4; gg++) {
            uint32_t bfr[4];
            int n = warp_n * 64 + gg * 16 + (lane & 7) + ((lane >> 4) & 1) * 8;
            uint32_t kb = (uint32_t)(kk * 32 + ((lane >> 3) & 1) * 16);
            LDMATRIX_X4(bfr, bBase + n * 256 + (kb ^ ((n & 7) << 4)));
            #pragma unroll
            for (int tm = 0; tm < 2; tm++) {
                MMA_FP8_F16(acc[tm][gg * 2],     afr[tm], bfr[0], bfr[1]);
                MMA_FP8_F16(acc[tm][gg * 2 + 1], afr[tm], bfr[2], bfr[3]);
            }
        }
    }

    const float DS = 1.f / 1024.f;

    if (!diag) {
        #pragma unroll
        for (int tm = 0; tm < 2; tm++) {
            float rs0 = 0.f, rs1 = 0.f;
            #pragma unroll
            for (int g = 0; g < 8; g++) {
                float2 e0 = __half22float2(*(const __half2*)&acc[tm][g][0]);
                float2 e1 = __half22float2(*(const __half2*)&acc[tm][g][1]);
                rs0 += __expf(e0.x * DS) + __expf(e0.y * DS);
                rs1 += __expf(e1.x * DS) + __expf(e1.y * DS);
            }
            rs0 += __shfl_xor_sync(0xffffffffu, rs0, 1);
            rs0 += __shfl_xor_sync(0xffffffffu, rs0, 2);
            rs1 += __shfl_xor_sync(0xffffffffu, rs1, 1);
            rs1 += __shfl_xor_sync(0xffffffffu, rs1, 2);
            if ((lane & 3) == 0) {
                int r = warp_m * 32 + tm * 16 + (lane >> 2);
                atomicAdd(&s_red[r], rs0);
                atomicAdd(&s_red[r + 8], rs1);
            }
        }
        __syncthreads();
        if (tid < 128) atomicAdd(&g_an[i * Tn + qt * 128 + tid], s_red[tid]);
    } else {
        #pragma unroll
        for (int g = 0; g < 8; g++) {
            float2 a00 = __half22float2(*(const __half2*)&acc[0][g][0]);
            float2 a01 = __half22float2(*(const __half2*)&acc[0][g][1]);
            float2 a10 = __half22float2(*(const __half2*)&acc[1][g][0]);
            float2 a11 = __half22float2(*(const __half2*)&acc[1][g][1]);
            float cs0 = __expf(a00.x * DS) + __expf(a01.x * DS)
                      + __expf(a10.x * DS) + __expf(a11.x * DS);
            float cs1 = __expf(a00.y * DS) + __expf(a01.y * DS)
                      + __expf(a10.y * DS) + __expf(a11.y * DS);
            cs0 += __shfl_xor_sync(0xffffffffu, cs0, 4);
            cs0 += __shfl_xor_sync(0xffffffffu, cs0, 8);
            cs0 += __shfl_xor_sync(0xffffffffu, cs0, 16);
            cs1 += __shfl_xor_sync(0xffffffffu, cs1, 4);
            cs1 += __shfl_xor_sync(0xffffffffu, cs1, 8);
            cs1 += __shfl_xor_sync(0xffffffffu, cs1, 16);
            if (lane < 4) {
                int c = warp_n * 64 + g * 8 + lane * 2;
                atomicAdd(&s_red[c], cs0);
                atomicAdd(&s_red[c + 1], cs1);
            }
        }
        __syncthreads();
        if (tid < 128) atomicAdd(&g_ap[i * Tn + kt * 128 + tid], s_red[tid]);
    }

    // ---- fused loss: last of 8192 CTAs reduces and resets counters ----
    __syncthreads();
    if (tid == 0) {
        __threadfence();
        s_old = atomicAdd(&g_done, 1u);
    }
    __syncthreads();
    if (s_old == MAIN_CTAS - 1) {
        __threadfence();
        float s = 0.f;
        for (int idx = tid; idx < Bn * Tn; idx += 256)
            s += logf(g_an[idx]) - logf(g_ap[idx]);
        float* red = (float*)smem;   // MMA done; reuse dynamic smem
        red[tid] = s;
        __syncthreads();
        for (int m = 128; m > 0; m >>= 1) {
            if (tid < m) red[tid] += red[tid + m];
            __syncthreads();
        }
        if (tid == 0) {
            out[0] = red[0] / (float)Tn;
            g_done = 0;
            #pragma unroll
            for (int k = 0; k < Vn; k++) g_cntV[k] = 0;   // for graph replay
        }
    }
}

// ---------------- launch (same-stream PDL; no stream/event creation) ----------------
extern "C" void kernel_launch(void* const* d_in, const int* in_sizes, int n_in,
                              void* d_out, int out_size) {
    const float* f  = (const float*)d_in[0];
    const float* fa = (const float*)d_in[1];

    cudaFuncSetAttribute(infonce_fp8h_kernel,
                         cudaFuncAttributeMaxDynamicSharedMemorySize, SMEM_DYN);

    zero_kernel<<<1, 256>>>();
    cvt_kernel<<<Vn * CVT_PER_V, 256>>>(f, fa);

    cudaLaunchConfig_t cfg = {};
    cfg.gridDim  = dim3(4, Bn * Bn, Vn);   // (qt+2kt, ij, v) — v slowest
    cfg.blockDim = dim3(256, 1, 1);
    cfg.dynamicSmemBytes = SMEM_DYN;
    cfg.stream = 0;
    cudaLaunchAttribute at[1];
    at[0].id = cudaLaunchAttributeProgrammaticStreamSerialization;
    at[0].val.programmaticStreamSerializationAllowed = 1;
    cfg.attrs = at;
    cfg.numAttrs = 1;

    cudaError_t e = cudaLaunchKernelEx(&cfg, infonce_fp8h_kernel, (float*)d_out);
    if (e != cudaSuccess) {
        cudaGetLastError();   // clear; plain serialized launch is still correct
        dim3 grid(4, Bn * Bn, Vn);
        infonce_fp8h_kernel<<<grid, 256, SMEM_DYN>>>((float*)d_out);
    }
}

// round 14
// speedup vs baseline: 1.0348x; 1.0348x over previous
#include <cuda_runtime.h>
#include <cuda_fp8.h>
#include <cuda_fp16.h>
#include <cstdint>
#include <math.h>

#define Bn 8
#define Tn 256
#define Vn 32
#define Dn 256
#define MAIN_CTAS 8192     // 4 * 32 * 64

// ---------------- device scratch (allocation-free) ----------------
__device__ float g_an[Bn * Tn];   // sum_{j!=i,v,k} exp(s) per (i,q)
__device__ float g_ap[Bn * Tn];   // sum_{v,q} exp(s_diag) per (i,k)
__device__ uint8_t g_fb8 [Bn * Tn * Vn * Dn];  // e4m3 feature      (x32 scaled)
__device__ uint8_t g_fab8[Bn * Tn * Vn * Dn];  // e4m3 feature_aug  (x32 scaled)
__device__ unsigned g_done;                     // main-CTA completion counter

// ---------------- PTX helpers (baseline ISA, sm_89/90 features) ----------------
__device__ __forceinline__ uint32_t smem_to_u32(const void* p) {
    uint32_t a;
    asm("{ .reg .u64 t; cvta.to.shared.u64 t, %1; cvt.u32.u64 %0, t; }"
        : "=r"(a) : "l"(p));
    return a;
}

#define CP_ASYNC16(saddr, gptr) \
    asm volatile("cp.async.cg.shared.global [%0], [%1], 16;" \
        :: "r"(saddr), "l"(gptr))
#define CP_COMMIT() asm volatile("cp.async.commit_group;")
#define CP_WAIT0()  asm volatile("cp.async.wait_group 0;")

#define LDMATRIX_X4(r, addr) \
    asm volatile("ldmatrix.sync.aligned.m8n8.x4.shared.b16 {%0,%1,%2,%3}, [%4];" \
        : "=r"((r)[0]), "=r"((r)[1]), "=r"((r)[2]), "=r"((r)[3]) : "r"(addr))

// fp8 e4m3 MMA with FP16 accumulator: D(2xb32 = 4xf16) += A * B
#define MMA_FP8_F16(d, a, b0, b1) \
    asm volatile("mma.sync.aligned.m16n8k32.row.col.f16.e4m3.e4m3.f16 " \
        "{%0,%1}, {%2,%3,%4,%5}, {%6,%7}, {%0,%1};" \
        : "+r"((d)[0]), "+r"((d)[1]) \
        : "r"((a)[0]), "r"((a)[1]), "r"((a)[2]), "r"((a)[3]), "r"(b0), "r"(b1))

// ---------------- layout ----------------
// fp8: full K=256 = 256B per row. A tile 128x256B = 32KB, B tile 128x256B = 32KB.
#define A_BYTES 32768
#define B_BYTES 32768
#define SMEM_DYN (A_BYTES + B_BYTES)   // 64 KB -> 2 CTAs/SM

// ---------------- kernels ----------------
__global__ void cvt_kernel(const float* __restrict__ f, const float* __restrict__ fa) {
    int idx = blockIdx.x * blockDim.x + threadIdx.x;
    const int N4 = Bn * Tn * Vn * Dn / 4;
    if (idx < N4) {
        float4 a = ((const float4*)f)[idx];
        float4 b = ((const float4*)fa)[idx];
        a.x *= 32.f; a.y *= 32.f; a.z *= 32.f; a.w *= 32.f;
        b.x *= 32.f; b.y *= 32.f; b.z *= 32.f; b.w *= 32.f;
        ((uint32_t*)g_fb8 )[idx] = __nv_fp8x4_e4m3(a).__x;
        ((uint32_t*)g_fab8)[idx] = __nv_fp8x4_e4m3(b).__x;
    }
    if (idx < Bn * Tn) { g_an[idx] = 0.f; g_ap[idx] = 0.f; }
    if (idx == Bn * Tn) g_done = 0u;
}

// One CTA: S[128,128] = A[128,256] @ B[128,256]^T (fp8 x32, f16 accum) for one
// (i,j,v,qt,kt); exp(S/1024) + row/col reductions. 8 warps, warp tile 32x64.
// Last CTA computes the final loss scalar (fused).
__global__ void __launch_bounds__(256, 2) infonce_fp8h_kernel(float* __restrict__ out) {
    extern __shared__ char smem[];
    __shared__ float s_red[128];
    __shared__ unsigned s_old;

    const uint32_t aBase = smem_to_u32(smem);
    const uint32_t bBase = aBase + A_BYTES;
    const int tid  = threadIdx.x;
    const int wid  = tid >> 5;
    const int lane = tid & 31;
    const int warp_m = wid >> 1;   // 0..3 -> m*32
    const int warp_n = wid & 1;    // 0..1 -> n*64

    const int qt = blockIdx.x & 1;
    const int kt = blockIdx.x >> 1;
    const int v  = blockIdx.y;
    const int i  = blockIdx.z >> 3;
    const int j  = blockIdx.z & 7;
    const bool diag = (i == j);

    if (tid < 128) s_red[tid] = 0.f;

    const size_t RS = (size_t)Vn * Dn;  // 8192 bytes between consecutive t
    const uint8_t* Ag = g_fb8  + ((size_t)(i * Tn + qt * 128) * Vn + v) * Dn;
    const uint8_t* Bg = g_fab8 + ((size_t)(j * Tn + kt * 128) * Vn + v) * Dn;

    // ---- load full tiles: 2048 16B chunks each, swizzled rows of 256B ----
    #pragma unroll
    for (int it = 0; it < 8; it++) {
        int id = tid + it * 256;
        int row = id >> 4, c = id & 15;
        uint32_t soff = (uint32_t)(row * 256) + (uint32_t)((c * 16) ^ ((row & 7) << 4));
        CP_ASYNC16(aBase + soff, Ag + (size_t)row * RS + c * 16);
    }
    #pragma unroll
    for (int it = 0; it < 8; it++) {
        int id = tid + it * 256;
        int row = id >> 4, c = id & 15;
        uint32_t soff = (uint32_t)(row * 256) + (uint32_t)((c * 16) ^ ((row & 7) << 4));
        CP_ASYNC16(bBase + soff, Bg + (size_t)row * RS + c * 16);
    }
    CP_COMMIT();

    // f16 accumulators: [tm][g][2 b32] = 4 halves each
    uint32_t acc[2][8][2];
    #pragma unroll
    for (int tm = 0; tm < 2; tm++)
        #pragma unroll
        for (int g = 0; g < 8; g++) { acc[tm][g][0] = 0u; acc[tm][g][1] = 0u; }

    CP_WAIT0();
    __syncthreads();

    // ---- 8 k-steps of 32 fp8 each ----
    #pragma unroll
    for (int kk = 0; kk < 8; kk++) {
        uint32_t afr[2][4];
        #pragma unroll
        for (int tm = 0; tm < 2; tm++) {
            int r = warp_m * 32 + tm * 16 + (lane & 7) + ((lane >> 3) & 1) * 8;
            uint32_t kb = (uint32_t)(kk * 32 + ((lane >> 4) & 1) * 16);
            LDMATRIX_X4(afr[tm], aBase + r * 256 + (kb ^ ((r & 7) << 4)));
        }
        #pragma unroll
        for (int gg = 0; gg < 4; gg++) {
            uint32_t bfr[4];
            int n = warp_n * 64 + gg * 16 + (lane & 7) + ((lane >> 4) & 1) * 8;
            uint32_t kb = (uint32_t)(kk * 32 + ((lane >> 3) & 1) * 16);
            LDMATRIX_X4(bfr, bBase + n * 256 + (kb ^ ((n & 7) << 4)));
            #pragma unroll
            for (int tm = 0; tm < 2; tm++) {
                MMA_FP8_F16(acc[tm][gg * 2],     afr[tm], bfr[0], bfr[1]);
                MMA_FP8_F16(acc[tm][gg * 2 + 1], afr[tm], bfr[2], bfr[3]);
            }
        }
    }

    // ---- epilogue: unpack f16, descale, exp, reductions ----
    // acc[tm][g]: reg0 = cols (c0,c0+1) @ row r0 = warp_m*32+tm*16+lane/4
    //             reg1 = same cols @ row r0+8;  c0 = warp_n*64+g*8+(lane&3)*2
    const float DS = 1.f / 1024.f;   // undo (32x)^2 input scaling

    if (!diag) {
        // negatives: row sums over this CTA's 128 k-cols
        #pragma unroll
        for (int tm = 0; tm < 2; tm++) {
            float rs0 = 0.f, rs1 = 0.f;
            #pragma unroll
            for (int g = 0; g < 8; g++) {
                float2 e0 = __half22float2(*(const __half2*)&acc[tm][g][0]);
                float2 e1 = __half22float2(*(const __half2*)&acc[tm][g][1]);
                rs0 += __expf(e0.x * DS) + __expf(e0.y * DS);
                rs1 += __expf(e1.x * DS) + __expf(e1.y * DS);
            }
            rs0 += __shfl_xor_sync(0xffffffffu, rs0, 1);
            rs0 += __shfl_xor_sync(0xffffffffu, rs0, 2);
            rs1 += __shfl_xor_sync(0xffffffffu, rs1, 1);
            rs1 += __shfl_xor_sync(0xffffffffu, rs1, 2);
            if ((lane & 3) == 0) {
                int r = warp_m * 32 + tm * 16 + (lane >> 2);
                atomicAdd(&s_red[r], rs0);
                atomicAdd(&s_red[r + 8], rs1);
            }
        }
        __syncthreads();
        if (tid < 128) atomicAdd(&g_an[i * Tn + qt * 128 + tid], s_red[tid]);
    } else {
        // positives: col sums over this CTA's 128 q-rows
        #pragma unroll
        for (int g = 0; g < 8; g++) {
            float2 a00 = __half22float2(*(const __half2*)&acc[0][g][0]);
            float2 a01 = __half22float2(*(const __half2*)&acc[0][g][1]);
            float2 a10 = __half22float2(*(const __half2*)&acc[1][g][0]);
            float2 a11 = __half22float2(*(const __half2*)&acc[1][g][1]);
            float cs0 = __expf(a00.x * DS) + __expf(a01.x * DS)
                      + __expf(a10.x * DS) + __expf(a11.x * DS);
            float cs1 = __expf(a00.y * DS) + __expf(a01.y * DS)
                      + __expf(a10.y * DS) + __expf(a11.y * DS);
            cs0 += __shfl_xor_sync(0xffffffffu, cs0, 4);
            cs0 += __shfl_xor_sync(0xffffffffu, cs0, 8);
            cs0 += __shfl_xor_sync(0xffffffffu, cs0, 16);
            cs1 += __shfl_xor_sync(0xffffffffu, cs1, 4);
            cs1 += __shfl_xor_sync(0xffffffffu, cs1, 8);
            cs1 += __shfl_xor_sync(0xffffffffu, cs1, 16);
            if (lane < 4) {
                int c = warp_n * 64 + g * 8 + lane * 2;
                atomicAdd(&s_red[c], cs0);
                atomicAdd(&s_red[c + 1], cs1);
            }
        }
        __syncthreads();
        if (tid < 128) atomicAdd(&g_ap[i * Tn + kt * 128 + tid], s_red[tid]);
    }

    // ---- fused loss: last of 8192 CTAs reduces and resets the counter ----
    __syncthreads();
    if (tid == 0) {
        __threadfence();
        s_old = atomicAdd(&g_done, 1u);
    }
    __syncthreads();
    if (s_old == MAIN_CTAS - 1) {
        __threadfence();   // all g_an/g_ap updates visible
        float s = 0.f;
        for (int idx = tid; idx < Bn * Tn; idx += 256)
            s += logf(g_an[idx]) - logf(g_ap[idx]);
        float* red = (float*)smem;   // MMA done; reuse dynamic smem
        red[tid] = s;
        __syncthreads();
        for (int m = 128; m > 0; m >>= 1) {
            if (tid < m) red[tid] += red[tid + m];
            __syncthreads();
        }
        if (tid == 0) {
            out[0] = red[0] / (float)Tn;
            g_done = 0;   // reset for graph replay
        }
    }
}

// ---------------- launch ----------------
extern "C" void kernel_launch(void* const* d_in, const int* in_sizes, int n_in,
                              void* d_out, int out_size) {
    const float* f  = (const float*)d_in[0];   // feature     [B,T,V,D]
    const float* fa = (const float*)d_in[1];   // feature_aug [B,T,V,D]

    cvt_kernel<<<(Bn * Tn * Vn * Dn / 4 + 255) / 256, 256>>>(f, fa);

    cudaFuncSetAttribute(infonce_fp8h_kernel,
                         cudaFuncAttributeMaxDynamicSharedMemorySize, SMEM_DYN);
    dim3 grid(4, Vn, Bn * Bn);   // (qt + 2*kt, v, i*8+j)
    infonce_fp8h_kernel<<<grid, 256, SMEM_DYN>>>((float*)d_out);
}

// round 15
// speedup vs baseline: 1.1163x; 1.0788x over previous
#include <cuda_runtime.h>
#include <cuda_fp8.h>
#include <cuda_fp16.h>
#include <cstdint>
#include <math.h>

#define Bn 8
#define Tn 256
#define Vn 32
#define Dn 256

// ---------------- device scratch (allocation-free) ----------------
__device__ float g_an[Bn * Tn];   // sum_{j!=i,v,k} exp(s) per (i,q)
__device__ float g_ap[Bn * Tn];   // sum_{v,q} exp(s_diag) per (i,k)
__device__ uint8_t g_fb8 [Bn * Tn * Vn * Dn];  // e4m3 feature      (x32 scaled)
__device__ uint8_t g_fab8[Bn * Tn * Vn * Dn];  // e4m3 feature_aug  (x32 scaled)

// ---------------- PTX helpers (baseline ISA, sm_89/90 features) ----------------
__device__ __forceinline__ uint32_t smem_to_u32(const void* p) {
    uint32_t a;
    asm("{ .reg .u64 t; cvta.to.shared.u64 t, %1; cvt.u32.u64 %0, t; }"
        : "=r"(a) : "l"(p));
    return a;
}

#define CP_ASYNC16(saddr, gptr) \
    asm volatile("cp.async.cg.shared.global [%0], [%1], 16;" \
        :: "r"(saddr), "l"(gptr))
#define CP_COMMIT() asm volatile("cp.async.commit_group;")
#define CP_WAIT0()  asm volatile("cp.async.wait_group 0;")

#define LDMATRIX_X4(r, addr) \
    asm volatile("ldmatrix.sync.aligned.m8n8.x4.shared.b16 {%0,%1,%2,%3}, [%4];" \
        : "=r"((r)[0]), "=r"((r)[1]), "=r"((r)[2]), "=r"((r)[3]) : "r"(addr))

// fp8 e4m3 MMA with FP16 accumulator: D(2xb32 = 4xf16) += A * B
#define MMA_FP8_F16(d, a, b0, b1) \
    asm volatile("mma.sync.aligned.m16n8k32.row.col.f16.e4m3.e4m3.f16 " \
        "{%0,%1}, {%2,%3,%4,%5}, {%6,%7}, {%0,%1};" \
        : "+r"((d)[0]), "+r"((d)[1]) \
        : "r"((a)[0]), "r"((a)[1]), "r"((a)[2]), "r"((a)[3]), "r"(b0), "r"(b1))

// ---------------- layout ----------------
#define A_BYTES 32768
#define B_BYTES 32768
#define SMEM_DYN (A_BYTES + B_BYTES)   // 64 KB -> 2 CTAs/SM

// ---------------- kernels ----------------
__global__ void cvt_kernel(const float* __restrict__ f, const float* __restrict__ fa) {
    int idx = blockIdx.x * blockDim.x + threadIdx.x;
    const int N4 = Bn * Tn * Vn * Dn / 4;
    if (idx < N4) {
        float4 a = ((const float4*)f)[idx];
        float4 b = ((const float4*)fa)[idx];
        a.x *= 32.f; a.y *= 32.f; a.z *= 32.f; a.w *= 32.f;
        b.x *= 32.f; b.y *= 32.f; b.z *= 32.f; b.w *= 32.f;
        ((uint32_t*)g_fb8 )[idx] = __nv_fp8x4_e4m3(a).__x;
        ((uint32_t*)g_fab8)[idx] = __nv_fp8x4_e4m3(b).__x;
    }
    if (idx < Bn * Tn) { g_an[idx] = 0.f; g_ap[idx] = 0.f; }
}

// One CTA: S[128,128] = A[128,256] @ B[128,256]^T (fp8 x32, f16 accum) for one
// (i,j,v,qt,kt); exp(S/1024) + row/col reductions. 8 warps, warp tile 32x64.
// Mainloop software-pipelines ldmatrix fragments one kk-step ahead.
__global__ void __launch_bounds__(256, 2) infonce_fp8p_kernel() {
    extern __shared__ char smem[];
    __shared__ float s_red[128];

    const uint32_t aBase = smem_to_u32(smem);
    const uint32_t bBase = aBase + A_BYTES;
    const int tid  = threadIdx.x;
    const int wid  = tid >> 5;
    const int lane = tid & 31;
    const int warp_m = wid >> 1;   // 0..3 -> m*32
    const int warp_n = wid & 1;    // 0..1 -> n*64

    const int qt = blockIdx.x & 1;
    const int kt = blockIdx.x >> 1;
    const int v  = blockIdx.y;
    const int i  = blockIdx.z >> 3;
    const int j  = blockIdx.z & 7;
    const bool diag = (i == j);

    if (tid < 128) s_red[tid] = 0.f;

    const size_t RS = (size_t)Vn * Dn;  // 8192 bytes between consecutive t
    const uint8_t* Ag = g_fb8  + ((size_t)(i * Tn + qt * 128) * Vn + v) * Dn;
    const uint8_t* Bg = g_fab8 + ((size_t)(j * Tn + kt * 128) * Vn + v) * Dn;

    // ---- load full tiles: 2048 16B chunks each, swizzled rows of 256B ----
    #pragma unroll
    for (int it = 0; it < 8; it++) {
        int id = tid + it * 256;
        int row = id >> 4, c = id & 15;
        uint32_t soff = (uint32_t)(row * 256) + (uint32_t)((c * 16) ^ ((row & 7) << 4));
        CP_ASYNC16(aBase + soff, Ag + (size_t)row * RS + c * 16);
    }
    #pragma unroll
    for (int it = 0; it < 8; it++) {
        int id = tid + it * 256;
        int row = id >> 4, c = id & 15;
        uint32_t soff = (uint32_t)(row * 256) + (uint32_t)((c * 16) ^ ((row & 7) << 4));
        CP_ASYNC16(bBase + soff, Bg + (size_t)row * RS + c * 16);
    }
    CP_COMMIT();

    // precomputed per-thread ldmatrix row addresses (kk-independent parts)
    uint32_t aRowAddr[2], bRowAddr[4];
    #pragma unroll
    for (int tm = 0; tm < 2; tm++) {
        int r = warp_m * 32 + tm * 16 + (lane & 7) + ((lane >> 3) & 1) * 8;
        aRowAddr[tm] = aBase + r * 256 + (uint32_t)((r & 7) << 4);  // XOR folded below
    }
    #pragma unroll
    for (int gg = 0; gg < 4; gg++) {
        int n = warp_n * 64 + gg * 16 + (lane & 7) + ((lane >> 4) & 1) * 8;
        bRowAddr[gg] = bBase + n * 256 + (uint32_t)((n & 7) << 4);
    }
    const uint32_t aKsel = (uint32_t)(((lane >> 4) & 1) * 16);
    const uint32_t bKsel = (uint32_t)(((lane >> 3) & 1) * 16);

    // NOTE: swizzled addr = base + r*256 + ((kb) ^ ((r&7)<<4)); we stored the
    // XOR mask pre-added, so per-kk we need base + r*256 + (kb ^ mask):
    // recompute via (addr - mask) + (kb ^ mask). To keep it exact, keep masks:
    uint32_t aMask[2], bMask[4];
    #pragma unroll
    for (int tm = 0; tm < 2; tm++) {
        int r = warp_m * 32 + tm * 16 + (lane & 7) + ((lane >> 3) & 1) * 8;
        aMask[tm] = (uint32_t)((r & 7) << 4);
        aRowAddr[tm] = aBase + r * 256;
    }
    #pragma unroll
    for (int gg = 0; gg < 4; gg++) {
        int n = warp_n * 64 + gg * 16 + (lane & 7) + ((lane >> 4) & 1) * 8;
        bMask[gg] = (uint32_t)((n & 7) << 4);
        bRowAddr[gg] = bBase + n * 256;
    }

    // f16 accumulators: [tm][g][2 b32] = 4 halves each
    uint32_t acc[2][8][2];
    #pragma unroll
    for (int tm = 0; tm < 2; tm++)
        #pragma unroll
        for (int g = 0; g < 8; g++) { acc[tm][g][0] = 0u; acc[tm][g][1] = 0u; }

    CP_WAIT0();
    __syncthreads();

    // ---- software-pipelined mainloop: fragments double-buffered over kk ----
    uint32_t afr[2][2][4];   // [buf][tm][4]
    uint32_t bfr[2][4][4];   // [buf][gg][4]

    // prologue: load kk=0 fragments into buffer 0
    #pragma unroll
    for (int tm = 0; tm < 2; tm++)
        LDMATRIX_X4(afr[0][tm], aRowAddr[tm] + (aKsel ^ aMask[tm]));
    #pragma unroll
    for (int gg = 0; gg < 4; gg++)
        LDMATRIX_X4(bfr[0][gg], bRowAddr[gg] + (bKsel ^ bMask[gg]));

    #pragma unroll
    for (int kk = 0; kk < 8; kk++) {
        const int cur = kk & 1;
        const int nxt = cur ^ 1;
        // prefetch kk+1 fragments (covers LDSM latency with the MMA burst below)
        if (kk < 7) {
            uint32_t kb = (uint32_t)((kk + 1) * 32);
            #pragma unroll
            for (int tm = 0; tm < 2; tm++)
                LDMATRIX_X4(afr[nxt][tm], aRowAddr[tm] + ((kb + aKsel) ^ aMask[tm]));
            #pragma unroll
            for (int gg = 0; gg < 4; gg++)
                LDMATRIX_X4(bfr[nxt][gg], bRowAddr[gg] + ((kb + bKsel) ^ bMask[gg]));
        }
        // 16 MMAs on current buffer
        #pragma unroll
        for (int gg = 0; gg < 4; gg++)
            #pragma unroll
            for (int tm = 0; tm < 2; tm++) {
                MMA_FP8_F16(acc[tm][gg * 2],     afr[cur][tm], bfr[cur][gg][0], bfr[cur][gg][1]);
                MMA_FP8_F16(acc[tm][gg * 2 + 1], afr[cur][tm], bfr[cur][gg][2], bfr[cur][gg][3]);
            }
    }

    // ---- epilogue: unpack f16, descale, exp, reductions ----
    // acc[tm][g]: reg0 = cols (c0,c0+1) @ row r0 = warp_m*32+tm*16+lane/4
    //             reg1 = same cols @ row r0+8;  c0 = warp_n*64+g*8+(lane&3)*2
    const float DS = 1.f / 1024.f;   // undo (32x)^2 input scaling

    if (!diag) {
        // negatives: row sums over this CTA's 128 k-cols
        #pragma unroll
        for (int tm = 0; tm < 2; tm++) {
            float rs0 = 0.f, rs1 = 0.f;
            #pragma unroll
            for (int g = 0; g < 8; g++) {
                float2 e0 = __half22float2(*(const __half2*)&acc[tm][g][0]);
                float2 e1 = __half22float2(*(const __half2*)&acc[tm][g][1]);
                rs0 += __expf(e0.x * DS) + __expf(e0.y * DS);
                rs1 += __expf(e1.x * DS) + __expf(e1.y * DS);
            }
            rs0 += __shfl_xor_sync(0xffffffffu, rs0, 1);
            rs0 += __shfl_xor_sync(0xffffffffu, rs0, 2);
            rs1 += __shfl_xor_sync(0xffffffffu, rs1, 1);
            rs1 += __shfl_xor_sync(0xffffffffu, rs1, 2);
            if ((lane & 3) == 0) {
                int r = warp_m * 32 + tm * 16 + (lane >> 2);
                atomicAdd(&s_red[r], rs0);
                atomicAdd(&s_red[r + 8], rs1);
            }
        }
        __syncthreads();
        if (tid < 128) atomicAdd(&g_an[i * Tn + qt * 128 + tid], s_red[tid]);
    } else {
        // positives: col sums over this CTA's 128 q-rows
        #pragma unroll
        for (int g = 0; g < 8; g++) {
            float2 a00 = __half22float2(*(const __half2*)&acc[0][g][0]);
            float2 a01 = __half22float2(*(const __half2*)&acc[0][g][1]);
            float2 a10 = __half22float2(*(const __half2*)&acc[1][g][0]);
            float2 a11 = __half22float2(*(const __half2*)&acc[1][g][1]);
            float cs0 = __expf(a00.x * DS) + __expf(a01.x * DS)
                      + __expf(a10.x * DS) + __expf(a11.x * DS);
            float cs1 = __expf(a00.y * DS) + __expf(a01.y * DS)
                      + __expf(a10.y * DS) + __expf(a11.y * DS);
            cs0 += __shfl_xor_sync(0xffffffffu, cs0, 4);
            cs0 += __shfl_xor_sync(0xffffffffu, cs0, 8);
            cs0 += __shfl_xor_sync(0xffffffffu, cs0, 16);
            cs1 += __shfl_xor_sync(0xffffffffu, cs1, 4);
            cs1 += __shfl_xor_sync(0xffffffffu, cs1, 8);
            cs1 += __shfl_xor_sync(0xffffffffu, cs1, 16);
            if (lane < 4) {
                int c = warp_n * 64 + g * 8 + lane * 2;
                atomicAdd(&s_red[c], cs0);
                atomicAdd(&s_red[c + 1], cs1);
            }
        }
        __syncthreads();
        if (tid < 128) atomicAdd(&g_ap[i * Tn + kt * 128 + tid], s_red[tid]);
    }
}

__global__ void loss_kernel(float* out) {
    __shared__ float red[256];
    int tid = threadIdx.x;
    float s = 0.f;
    for (int idx = tid; idx < Bn * Tn; idx += 256)
        s += logf(g_an[idx]) - logf(g_ap[idx]);
    red[tid] = s;
    __syncthreads();
    for (int m = 128; m > 0; m >>= 1) {
        if (tid < m) red[tid] += red[tid + m];
        __syncthreads();
    }
    if (tid == 0) out[0] = red[0] / (float)Tn;
}

// ---------------- launch ----------------
extern "C" void kernel_launch(void* const* d_in, const int* in_sizes, int n_in,
                              void* d_out, int out_size) {
    const float* f  = (const float*)d_in[0];   // feature     [B,T,V,D]
    const float* fa = (const float*)d_in[1];   // feature_aug [B,T,V,D]

    cvt_kernel<<<(Bn * Tn * Vn * Dn / 4 + 255) / 256, 256>>>(f, fa);

    cudaFuncSetAttribute(infonce_fp8p_kernel,
                         cudaFuncAttributeMaxDynamicSharedMemorySize, SMEM_DYN);
    dim3 grid(4, Vn, Bn * Bn);   // (qt + 2*kt, v, i*8+j)
    infonce_fp8p_kernel<<<grid, 256, SMEM_DYN>>>();

    loss_kernel<<<1, 256>>>((float*)d_out);
}

// round 16
// speedup vs baseline: 1.3100x; 1.1735x over previous
#include <cuda_runtime.h>
#include <cuda_fp8.h>
#include <cuda_fp16.h>
#include <cstdint>
#include <math.h>

#define Bn 8
#define Tn 256
#define Vn 32
#define Dn 256

// ---------------- device scratch (allocation-free) ----------------
__device__ float g_an[Bn * Tn];   // sum_{j!=i,v,k} exp(s) per (i,q)
__device__ float g_ap[Bn * Tn];   // sum_{v,q} exp(s_diag) per (i,k)
__device__ uint8_t g_fb8 [Bn * Tn * Vn * Dn];  // e4m3 feature      (x32*sqrt(log2e))
__device__ uint8_t g_fab8[Bn * Tn * Vn * Dn];  // e4m3 feature_aug  (x32*sqrt(log2e))

// ---------------- PTX helpers (baseline ISA, sm_89/90 features) ----------------
__device__ __forceinline__ uint32_t smem_to_u32(const void* p) {
    uint32_t a;
    asm("{ .reg .u64 t; cvta.to.shared.u64 t, %1; cvt.u32.u64 %0, t; }"
        : "=r"(a) : "l"(p));
    return a;
}

#define CP_ASYNC16(saddr, gptr) \
    asm volatile("cp.async.cg.shared.global [%0], [%1], 16;" \
        :: "r"(saddr), "l"(gptr))
#define CP_COMMIT() asm volatile("cp.async.commit_group;")
#define CP_WAIT0()  asm volatile("cp.async.wait_group 0;")

#define LDMATRIX_X4(r, addr) \
    asm volatile("ldmatrix.sync.aligned.m8n8.x4.shared.b16 {%0,%1,%2,%3}, [%4];" \
        : "=r"((r)[0]), "=r"((r)[1]), "=r"((r)[2]), "=r"((r)[3]) : "r"(addr))

// fp8 e4m3 MMA with FP16 accumulator: D(2xb32 = 4xf16) += A * B
#define MMA_FP8_F16(d, a, b0, b1) \
    asm volatile("mma.sync.aligned.m16n8k32.row.col.f16.e4m3.e4m3.f16 " \
        "{%0,%1}, {%2,%3,%4,%5}, {%6,%7}, {%0,%1};" \
        : "+r"((d)[0]), "+r"((d)[1]) \
        : "r"((a)[0]), "r"((a)[1]), "r"((a)[2]), "r"((a)[3]), "r"(b0), "r"(b1))

// 2-wide exp2 on packed halves
#define EX2_F16X2(d, x) \
    asm("ex2.approx.f16x2 %0, %1;" : "=r"(d) : "r"(x))

// ---------------- layout ----------------
#define A_BYTES 32768
#define B_BYTES 32768
#define SMEM_DYN (A_BYTES + B_BYTES)   // 64 KB; occ 3 -> 192 KB/SM dyn smem

// cvt scale: 32 * sqrt(log2(e))  => acc = s * 1024 * log2(e)
#define SC 38.435917f

// ---------------- kernels ----------------
__global__ void cvt_kernel(const float* __restrict__ f, const float* __restrict__ fa) {
    int idx = blockIdx.x * blockDim.x + threadIdx.x;
    const int N4 = Bn * Tn * Vn * Dn / 4;
    if (idx < N4) {
        float4 a = ((const float4*)f)[idx];
        float4 b = ((const float4*)fa)[idx];
        a.x *= SC; a.y *= SC; a.z *= SC; a.w *= SC;
        b.x *= SC; b.y *= SC; b.z *= SC; b.w *= SC;
        ((uint32_t*)g_fb8 )[idx] = __nv_fp8x4_e4m3(a).__x;
        ((uint32_t*)g_fab8)[idx] = __nv_fp8x4_e4m3(b).__x;
    }
    if (idx < Bn * Tn) { g_an[idx] = 0.f; g_ap[idx] = 0.f; }
}

// One CTA: S[128,128] = A[128,256] @ B[128,256]^T (fp8, f16 accum) for one
// (i,j,v,qt,kt). Epilogue in f16x2: HMUL2(2^-10) -> ex2.f16x2 -> HADD2 trees.
__global__ void __launch_bounds__(256, 3) infonce_fp8e_kernel() {
    extern __shared__ char smem[];
    __shared__ float s_red[128];

    const uint32_t aBase = smem_to_u32(smem);
    const uint32_t bBase = aBase + A_BYTES;
    const int tid  = threadIdx.x;
    const int wid  = tid >> 5;
    const int lane = tid & 31;
    const int warp_m = wid >> 1;   // 0..3 -> m*32
    const int warp_n = wid & 1;    // 0..1 -> n*64

    const int qt = blockIdx.x & 1;
    const int kt = blockIdx.x >> 1;
    const int v  = blockIdx.y;
    const int i  = blockIdx.z >> 3;
    const int j  = blockIdx.z & 7;
    const bool diag = (i == j);

    if (tid < 128) s_red[tid] = 0.f;

    const size_t RS = (size_t)Vn * Dn;  // 8192 bytes between consecutive t
    const uint8_t* Ag = g_fb8  + ((size_t)(i * Tn + qt * 128) * Vn + v) * Dn;
    const uint8_t* Bg = g_fab8 + ((size_t)(j * Tn + kt * 128) * Vn + v) * Dn;

    // ---- load full tiles: 2048 16B chunks each, swizzled rows of 256B ----
    #pragma unroll
    for (int it = 0; it < 8; it++) {
        int id = tid + it * 256;
        int row = id >> 4, c = id & 15;
        uint32_t soff = (uint32_t)(row * 256) + (uint32_t)((c * 16) ^ ((row & 7) << 4));
        CP_ASYNC16(aBase + soff, Ag + (size_t)row * RS + c * 16);
    }
    #pragma unroll
    for (int it = 0; it < 8; it++) {
        int id = tid + it * 256;
        int row = id >> 4, c = id & 15;
        uint32_t soff = (uint32_t)(row * 256) + (uint32_t)((c * 16) ^ ((row & 7) << 4));
        CP_ASYNC16(bBase + soff, Bg + (size_t)row * RS + c * 16);
    }
    CP_COMMIT();

    // hoisted ldmatrix row bases + swizzle masks
    uint32_t aRow[2], aMask[2], bRow[4], bMask[4];
    #pragma unroll
    for (int tm = 0; tm < 2; tm++) {
        int r = warp_m * 32 + tm * 16 + (lane & 7) + ((lane >> 3) & 1) * 8;
        aRow[tm] = aBase + r * 256;
        aMask[tm] = (uint32_t)((r & 7) << 4);
    }
    #pragma unroll
    for (int gg = 0; gg < 4; gg++) {
        int n = warp_n * 64 + gg * 16 + (lane & 7) + ((lane >> 4) & 1) * 8;
        bRow[gg] = bBase + n * 256;
        bMask[gg] = (uint32_t)((n & 7) << 4);
    }
    const uint32_t aKsel = (uint32_t)(((lane >> 4) & 1) * 16);
    const uint32_t bKsel = (uint32_t)(((lane >> 3) & 1) * 16);

    // f16 accumulators: [tm][g][2 b32] = 4 halves each
    uint32_t acc[2][8][2];
    #pragma unroll
    for (int tm = 0; tm < 2; tm++)
        #pragma unroll
        for (int g = 0; g < 8; g++) { acc[tm][g][0] = 0u; acc[tm][g][1] = 0u; }

    CP_WAIT0();
    __syncthreads();

    // ---- 8 k-steps of 32 fp8 each (R7 proven structure) ----
    #pragma unroll
    for (int kk = 0; kk < 8; kk++) {
        uint32_t afr[2][4];
        #pragma unroll
        for (int tm = 0; tm < 2; tm++) {
            uint32_t kb = (uint32_t)(kk * 32) + aKsel;
            LDMATRIX_X4(afr[tm], aRow[tm] + (kb ^ aMask[tm]));
        }
        #pragma unroll
        for (int gg = 0; gg < 4; gg++) {
            uint32_t bfr[4];
            uint32_t kb = (uint32_t)(kk * 32) + bKsel;
            LDMATRIX_X4(bfr, bRow[gg] + (kb ^ bMask[gg]));
            #pragma unroll
            for (int tm = 0; tm < 2; tm++) {
                MMA_FP8_F16(acc[tm][gg * 2],     afr[tm], bfr[0], bfr[1]);
                MMA_FP8_F16(acc[tm][gg * 2 + 1], afr[tm], bfr[2], bfr[3]);
            }
        }
    }

    // ---- epilogue (f16x2): acc holds s*1024*log2e; scale by exact 2^-10,
    // ex2 -> e^s, then HADD2 reduction trees ----
    const __half2 SCL = __half2half2(__ushort_as_half((unsigned short)0x1400)); // 2^-10

    // in-place: acc <- exp values (packed f16x2)
    #pragma unroll
    for (int tm = 0; tm < 2; tm++)
        #pragma unroll
        for (int g = 0; g < 8; g++)
            #pragma unroll
            for (int h = 0; h < 2; h++) {
                __half2 x = __hmul2(*(const __half2*)&acc[tm][g][h], SCL);
                EX2_F16X2(acc[tm][g][h], *(const uint32_t*)&x);
            }

    if (!diag) {
        // row sums: acc[tm][g][0] all share row r0 (cols vary); [1] row r0+8
        #pragma unroll
        for (int tm = 0; tm < 2; tm++) {
            #pragma unroll
            for (int h = 0; h < 2; h++) {
                __half2 p0 = __hadd2(*(const __half2*)&acc[tm][0][h], *(const __half2*)&acc[tm][1][h]);
                __half2 p1 = __hadd2(*(const __half2*)&acc[tm][2][h], *(const __half2*)&acc[tm][3][h]);
                __half2 p2 = __hadd2(*(const __half2*)&acc[tm][4][h], *(const __half2*)&acc[tm][5][h]);
                __half2 p3 = __hadd2(*(const __half2*)&acc[tm][6][h], *(const __half2*)&acc[tm][7][h]);
                __half2 s  = __hadd2(__hadd2(p0, p1), __hadd2(p2, p3));
                float2 sf = __half22float2(s);
                float rs = sf.x + sf.y;
                rs += __shfl_xor_sync(0xffffffffu, rs, 1);
                rs += __shfl_xor_sync(0xffffffffu, rs, 2);
                if ((lane & 3) == 0) {
                    int r = warp_m * 32 + tm * 16 + (lane >> 2) + h * 8;
                    atomicAdd(&s_red[r], rs);
                }
            }
        }
        __syncthreads();
        if (tid < 128) atomicAdd(&g_an[i * Tn + qt * 128 + tid], s_red[tid]);
    } else {
        // col sums: per g sum the 4 rows (tm x h) in f16, then f32 shuffles
        #pragma unroll
        for (int g = 0; g < 8; g++) {
            __half2 t = __hadd2(
                __hadd2(*(const __half2*)&acc[0][g][0], *(const __half2*)&acc[0][g][1]),
                __hadd2(*(const __half2*)&acc[1][g][0], *(const __half2*)&acc[1][g][1]));
            float2 tf = __half22float2(t);
            float cs0 = tf.x, cs1 = tf.y;
            cs0 += __shfl_xor_sync(0xffffffffu, cs0, 4);
            cs0 += __shfl_xor_sync(0xffffffffu, cs0, 8);
            cs0 += __shfl_xor_sync(0xffffffffu, cs0, 16);
            cs1 += __shfl_xor_sync(0xffffffffu, cs1, 4);
            cs1 += __shfl_xor_sync(0xffffffffu, cs1, 8);
            cs1 += __shfl_xor_sync(0xffffffffu, cs1, 16);
            if (lane < 4) {
                int c = warp_n * 64 + g * 8 + lane * 2;
                atomicAdd(&s_red[c], cs0);
                atomicAdd(&s_red[c + 1], cs1);
            }
        }
        __syncthreads();
        if (tid < 128) atomicAdd(&g_ap[i * Tn + kt * 128 + tid], s_red[tid]);
    }
}

__global__ void loss_kernel(float* out) {
    __shared__ float red[256];
    int tid = threadIdx.x;
    float s = 0.f;
    for (int idx = tid; idx < Bn * Tn; idx += 256)
        s += logf(g_an[idx]) - logf(g_ap[idx]);
    red[tid] = s;
    __syncthreads();
    for (int m = 128; m > 0; m >>= 1) {
        if (tid < m) red[tid] += red[tid + m];
        __syncthreads();
    }
    if (tid == 0) out[0] = red[0] / (float)Tn;
}

// ---------------- launch ----------------
extern "C" void kernel_launch(void* const* d_in, const int* in_sizes, int n_in,
                              void* d_out, int out_size) {
    const float* f  = (const float*)d_in[0];   // feature     [B,T,V,D]
    const float* fa = (const float*)d_in[1];   // feature_aug [B,T,V,D]

    cvt_kernel<<<(Bn * Tn * Vn * Dn / 4 + 255) / 256, 256>>>(f, fa);

    cudaFuncSetAttribute(infonce_fp8e_kernel,
                         cudaFuncAttributeMaxDynamicSharedMemorySize, SMEM_DYN);
    dim3 grid(4, Vn, Bn * Bn);   // (qt + 2*kt, v, i*8+j)
    infonce_fp8e_kernel<<<grid, 256, SMEM_DYN>>>();

    loss_kernel<<<1, 256>>>((float*)d_out);
}

// round 17
// speedup vs baseline: 1.3229x; 1.0099x over previous
#include <cuda_runtime.h>
#include <cuda_fp8.h>
#include <cuda_fp16.h>
#include <cstdint>
#include <math.h>

#define Bn 8
#define Tn 256
#define Vn 32
#define Dn 256

// ---------------- device scratch (allocation-free) ----------------
__device__ float g_an[Bn * Tn];   // sum_{j!=i,v,k} exp(s) per (i,q)
__device__ float g_ap[Bn * Tn];   // sum_{v,q} exp(s_diag) per (i,k)
__device__ uint8_t g_fb8 [Bn * Tn * Vn * Dn];  // e4m3 feature      (x32*sqrt(log2e))
__device__ uint8_t g_fab8[Bn * Tn * Vn * Dn];  // e4m3 feature_aug  (x32*sqrt(log2e))

// ---------------- PTX helpers (baseline ISA, sm_89/90 features) ----------------
__device__ __forceinline__ uint32_t smem_to_u32(const void* p) {
    uint32_t a;
    asm("{ .reg .u64 t; cvta.to.shared.u64 t, %1; cvt.u32.u64 %0, t; }"
        : "=r"(a) : "l"(p));
    return a;
}

#define CP_ASYNC16(saddr, gptr) \
    asm volatile("cp.async.cg.shared.global [%0], [%1], 16;" \
        :: "r"(saddr), "l"(gptr))
#define CP_COMMIT() asm volatile("cp.async.commit_group;")
#define CP_WAIT(n)  asm volatile("cp.async.wait_group %0;" :: "n"(n))

#define LDMATRIX_X4(r, addr) \
    asm volatile("ldmatrix.sync.aligned.m8n8.x4.shared.b16 {%0,%1,%2,%3}, [%4];" \
        : "=r"((r)[0]), "=r"((r)[1]), "=r"((r)[2]), "=r"((r)[3]) : "r"(addr))

// fp8 e4m3 MMA with FP16 accumulator: D(2xb32 = 4xf16) += A * B
#define MMA_FP8_F16(d, a, b0, b1) \
    asm volatile("mma.sync.aligned.m16n8k32.row.col.f16.e4m3.e4m3.f16 " \
        "{%0,%1}, {%2,%3,%4,%5}, {%6,%7}, {%0,%1};" \
        : "+r"((d)[0]), "+r"((d)[1]) \
        : "r"((a)[0]), "r"((a)[1]), "r"((a)[2]), "r"((a)[3]), "r"(b0), "r"(b1))

// 2-wide exp2 on packed halves
#define EX2_F16X2(d, x) \
    asm("ex2.approx.f16x2 %0, %1;" : "=r"(d) : "r"(x))

// ---------------- layout ----------------
// Two k-stages of 32 KB: [A half 16KB | B half 16KB], rows of 128 B.
#define HALF_A   16384
#define STAGE    32768
#define SMEM_DYN (2 * STAGE)   // 64 KB; occ 3 -> 192 KB/SM dyn smem

// cvt scale: 32 * sqrt(log2(e))  => acc = s * 1024 * log2(e)
#define SC 38.435917f

// ---------------- kernels ----------------
__global__ void cvt_kernel(const float* __restrict__ f, const float* __restrict__ fa) {
    int idx = blockIdx.x * blockDim.x + threadIdx.x;
    const int N4 = Bn * Tn * Vn * Dn / 4;
    if (idx < N4) {
        float4 a = ((const float4*)f)[idx];
        float4 b = ((const float4*)fa)[idx];
        a.x *= SC; a.y *= SC; a.z *= SC; a.w *= SC;
        b.x *= SC; b.y *= SC; b.z *= SC; b.w *= SC;
        ((uint32_t*)g_fb8 )[idx] = __nv_fp8x4_e4m3(a).__x;
        ((uint32_t*)g_fab8)[idx] = __nv_fp8x4_e4m3(b).__x;
    }
    if (idx < Bn * Tn) { g_an[idx] = 0.f; g_ap[idx] = 0.f; }
}

// One CTA: S[128,128] = A[128,256] @ B[128,256]^T (fp8, f16 accum) for one
// (i,j,v,qt,kt). K split into two cp.async-pipelined 128-wide halves.
// Epilogue in f16x2: HMUL2(2^-10) -> ex2.f16x2 -> HADD2 trees.
__global__ void __launch_bounds__(256, 3) infonce_fp8k_kernel() {
    extern __shared__ char smem[];
    __shared__ float s_red[128];

    const uint32_t base = smem_to_u32(smem);
    const int tid  = threadIdx.x;
    const int wid  = tid >> 5;
    const int lane = tid & 31;
    const int warp_m = wid >> 1;   // 0..3 -> m*32
    const int warp_n = wid & 1;    // 0..1 -> n*64

    const int qt = blockIdx.x & 1;
    const int kt = blockIdx.x >> 1;
    const int v  = blockIdx.y;
    const int i  = blockIdx.z >> 3;
    const int j  = blockIdx.z & 7;
    const bool diag = (i == j);

    if (tid < 128) s_red[tid] = 0.f;

    const size_t RS = (size_t)Vn * Dn;  // 8192 bytes between consecutive t
    const uint8_t* Ag = g_fb8  + ((size_t)(i * Tn + qt * 128) * Vn + v) * Dn;
    const uint8_t* Bg = g_fab8 + ((size_t)(j * Tn + kt * 128) * Vn + v) * Dn;

    // ---- pipelined loads: half h (d in [h*128, h*128+128)) into stage h ----
    #pragma unroll
    for (int h = 0; h < 2; h++) {
        const uint32_t sA = base + h * STAGE;
        const uint32_t sB = sA + HALF_A;
        #pragma unroll
        for (int it = 0; it < 4; it++) {             // A half: 1024 16B chunks
            int id = tid + it * 256;
            int row = id >> 3, c = id & 7;
            uint32_t soff = (uint32_t)(row * 128) + (uint32_t)((c * 16) ^ ((row & 7) << 4));
            CP_ASYNC16(sA + soff, Ag + (size_t)row * RS + h * 128 + c * 16);
        }
        #pragma unroll
        for (int it = 0; it < 4; it++) {             // B half
            int id = tid + it * 256;
            int row = id >> 3, c = id & 7;
            uint32_t soff = (uint32_t)(row * 128) + (uint32_t)((c * 16) ^ ((row & 7) << 4));
            CP_ASYNC16(sB + soff, Bg + (size_t)row * RS + h * 128 + c * 16);
        }
        CP_COMMIT();
    }

    // hoisted fragment row indices + swizzle masks (row stride 128B per stage)
    uint32_t aOff[2], aMask[2], bOff[4], bMask[4];
    #pragma unroll
    for (int tm = 0; tm < 2; tm++) {
        int r = warp_m * 32 + tm * 16 + (lane & 7) + ((lane >> 3) & 1) * 8;
        aOff[tm] = (uint32_t)(r * 128);
        aMask[tm] = (uint32_t)((r & 7) << 4);
    }
    #pragma unroll
    for (int gg = 0; gg < 4; gg++) {
        int n = warp_n * 64 + gg * 16 + (lane & 7) + ((lane >> 4) & 1) * 8;
        bOff[gg] = (uint32_t)(n * 128);
        bMask[gg] = (uint32_t)((n & 7) << 4);
    }
    const uint32_t aKsel = (uint32_t)(((lane >> 4) & 1) * 16);
    const uint32_t bKsel = (uint32_t)(((lane >> 3) & 1) * 16);

    // f16 accumulators: [tm][g][2 b32] = 4 halves each
    uint32_t acc[2][8][2];
    #pragma unroll
    for (int tm = 0; tm < 2; tm++)
        #pragma unroll
        for (int g = 0; g < 8; g++) { acc[tm][g][0] = 0u; acc[tm][g][1] = 0u; }

    // ---- compute half 0 while half 1 is still in flight ----
    #pragma unroll
    for (int h = 0; h < 2; h++) {
        if (h == 0) CP_WAIT(1);
        else        CP_WAIT(0);
        __syncthreads();

        const uint32_t sA = base + h * STAGE;
        const uint32_t sB = sA + HALF_A;

        #pragma unroll
        for (int kk = 0; kk < 4; kk++) {
            uint32_t afr[2][4];
            #pragma unroll
            for (int tm = 0; tm < 2; tm++) {
                uint32_t kb = (uint32_t)(kk * 32) + aKsel;
                LDMATRIX_X4(afr[tm], sA + aOff[tm] + (kb ^ aMask[tm]));
            }
            #pragma unroll
            for (int gg = 0; gg < 4; gg++) {
                uint32_t bfr[4];
                uint32_t kb = (uint32_t)(kk * 32) + bKsel;
                LDMATRIX_X4(bfr, sB + bOff[gg] + (kb ^ bMask[gg]));
                #pragma unroll
                for (int tm = 0; tm < 2; tm++) {
                    MMA_FP8_F16(acc[tm][gg * 2],     afr[tm], bfr[0], bfr[1]);
                    MMA_FP8_F16(acc[tm][gg * 2 + 1], afr[tm], bfr[2], bfr[3]);
                }
            }
        }
    }

    // ---- epilogue (f16x2): acc holds s*1024*log2e; scale by exact 2^-10,
    // ex2 -> e^s, then HADD2 reduction trees ----
    const __half2 SCL = __half2half2(__ushort_as_half((unsigned short)0x1400)); // 2^-10

    #pragma unroll
    for (int tm = 0; tm < 2; tm++)
        #pragma unroll
        for (int g = 0; g < 8; g++)
            #pragma unroll
            for (int h = 0; h < 2; h++) {
                __half2 x = __hmul2(*(const __half2*)&acc[tm][g][h], SCL);
                EX2_F16X2(acc[tm][g][h], *(const uint32_t*)&x);
            }

    if (!diag) {
        // row sums: acc[tm][g][0] row r0; acc[tm][g][1] row r0+8
        #pragma unroll
        for (int tm = 0; tm < 2; tm++) {
            #pragma unroll
            for (int h = 0; h < 2; h++) {
                __half2 p0 = __hadd2(*(const __half2*)&acc[tm][0][h], *(const __half2*)&acc[tm][1][h]);
                __half2 p1 = __hadd2(*(const __half2*)&acc[tm][2][h], *(const __half2*)&acc[tm][3][h]);
                __half2 p2 = __hadd2(*(const __half2*)&acc[tm][4][h], *(const __half2*)&acc[tm][5][h]);
                __half2 p3 = __hadd2(*(const __half2*)&acc[tm][6][h], *(const __half2*)&acc[tm][7][h]);
                __half2 s  = __hadd2(__hadd2(p0, p1), __hadd2(p2, p3));
                float2 sf = __half22float2(s);
                float rs = sf.x + sf.y;
                rs += __shfl_xor_sync(0xffffffffu, rs, 1);
                rs += __shfl_xor_sync(0xffffffffu, rs, 2);
                if ((lane & 3) == 0) {
                    int r = warp_m * 32 + tm * 16 + (lane >> 2) + h * 8;
                    atomicAdd(&s_red[r], rs);
                }
            }
        }
        __syncthreads();
        if (tid < 128) atomicAdd(&g_an[i * Tn + qt * 128 + tid], s_red[tid]);
    } else {
        // col sums: per g sum the 4 rows (tm x h) in f16, then f32 shuffles
        #pragma unroll
        for (int g = 0; g < 8; g++) {
            __half2 t = __hadd2(
                __hadd2(*(const __half2*)&acc[0][g][0], *(const __half2*)&acc[0][g][1]),
                __hadd2(*(const __half2*)&acc[1][g][0], *(const __half2*)&acc[1][g][1]));
            float2 tf = __half22float2(t);
            float cs0 = tf.x, cs1 = tf.y;
            cs0 += __shfl_xor_sync(0xffffffffu, cs0, 4);
            cs0 += __shfl_xor_sync(0xffffffffu, cs0, 8);
            cs0 += __shfl_xor_sync(0xffffffffu, cs0, 16);
            cs1 += __shfl_xor_sync(0xffffffffu, cs1, 4);
            cs1 += __shfl_xor_sync(0xffffffffu, cs1, 8);
            cs1 += __shfl_xor_sync(0xffffffffu, cs1, 16);
            if (lane < 4) {
                int c = warp_n * 64 + g * 8 + lane * 2;
                atomicAdd(&s_red[c], cs0);
                atomicAdd(&s_red[c + 1], cs1);
            }
        }
        __syncthreads();
        if (tid < 128) atomicAdd(&g_ap[i * Tn + kt * 128 + tid], s_red[tid]);
    }
}

__global__ void loss_kernel(float* out) {
    __shared__ float red[256];
    int tid = threadIdx.x;
    float s = 0.f;
    for (int idx = tid; idx < Bn * Tn; idx += 256)
        s += logf(g_an[idx]) - logf(g_ap[idx]);
    red[tid] = s;
    __syncthreads();
    for (int m = 128; m > 0; m >>= 1) {
        if (tid < m) red[tid] += red[tid + m];
        __syncthreads();
    }
    if (tid == 0) out[0] = red[0] / (float)Tn;
}

// ---------------- launch ----------------
extern "C" void kernel_launch(void* const* d_in, const int* in_sizes, int n_in,
                              void* d_out, int out_size) {
    const float* f  = (const float*)d_in[0];   // feature     [B,T,V,D]
    const float* fa = (const float*)d_in[1];   // feature_aug [B,T,V,D]

    cvt_kernel<<<(Bn * Tn * Vn * Dn / 4 + 255) / 256, 256>>>(f, fa);

    cudaFuncSetAttribute(infonce_fp8k_kernel,
                         cudaFuncAttributeMaxDynamicSharedMemorySize, SMEM_DYN);
    dim3 grid(4, Vn, Bn * Bn);   // (qt + 2*kt, v, i*8+j)
    infonce_fp8k_kernel<<<grid, 256, SMEM_DYN>>>();

    loss_kernel<<<1, 256>>>((float*)d_out);
}